// round 8
// baseline (speedup 1.0000x reference)
#include <cuda_runtime.h>

#define NPIX (512*512)
#define D1B 6
#define D1S 3
#define MAXMB (D1B*NPIX+1)
#define MAXMS (D1S*NPIX+1)
#define ALPHA_B (32.0f/33.0f)
#define ALPHA_S 0.8f
#define BI_COMPAT 10.0f
#define SP_COMPAT 3.0f
#define TPB 512
#define MAXBLK 592   // 148 SMs x 4 co-resident blocks @ launch_bounds(512,4)

// float4 tables for Q filtering (3-buffer ping-pong per lattice).
__device__ float4 g_tb[3][MAXMB];
__device__ float4 g_ts[3][MAXMS];
// fp32 scalar tables for the prologue ones-filter.
__device__ float  g_sb[2][MAXMB];
__device__ float  g_ss[2][MAXMS];
// Composed 2-pass stencil indices: bilateral pairs (0,1),(2,3),(4,5); spatial pair (0,1).
__device__ int    g_cb[3][(size_t)(MAXMB - 1) * 8];
__device__ int    g_cs9[(size_t)(MAXMS - 1) * 8];
__device__ float4 g_msgS[NPIX];
__device__ float  g_inb[NPIX];
__device__ float  g_ins[NPIX];

// Software grid barrier state.
__device__ unsigned g_count = 0;
__device__ volatile unsigned g_gen = 0;

__device__ __forceinline__ void gsync(unsigned nb) {
    __syncthreads();
    if (threadIdx.x == 0) {
        __threadfence();                       // release my writes (incl. RED) to L2
        unsigned my = g_gen;
        if (atomicInc(&g_count, nb - 1u) == nb - 1u) {
            g_gen = my + 1u;                   // last arriver releases everyone
        } else {
            while (g_gen == my) __nanosleep(64);
        }
        __threadfence();
    }
    __syncthreads();
}

__device__ __forceinline__ void red4(float4* p, float x, float y, float z, float w) {
    asm volatile("red.global.add.v4.f32 [%0], {%1,%2,%3,%4};"
                 :: "l"(p), "f"(x), "f"(y), "f"(z), "f"(w) : "memory");
}
__device__ __forceinline__ void red1(float* p, float v) {
    asm volatile("red.global.add.f32 [%0], %1;" :: "l"(p), "f"(v) : "memory");
}

__device__ __forceinline__ float4 softmax_neg(float4 u, float4 msg) {
    float zx = msg.x - u.x, zy = msg.y - u.y, zz = msg.z - u.z, zw = msg.w - u.w;
    float m = fmaxf(fmaxf(zx, zy), fmaxf(zz, zw));
    float ex = __expf(zx - m), ey = __expf(zy - m), ez = __expf(zz - m), ew = __expf(zw - m);
    float inv = 1.0f / (ex + ey + ez + ew);
    return make_float4(ex * inv, ey * inv, ez * inv, ew * inv);
}

// 9-tap composed gather; table values via L2 (__ldcg) for cross-phase coherence.
__device__ __forceinline__ float4 g9(const int* __restrict__ idx8,
                                     const float4* __restrict__ s, int center) {
    int4 i0 = *(const int4*)(idx8);
    int4 i1 = *(const int4*)(idx8 + 4);
    float4 c  = __ldcg(s + center);
    float4 a0 = __ldcg(s + i0.x), a1 = __ldcg(s + i0.y);
    float4 n1 = __ldcg(s + i0.z), n1a = __ldcg(s + i0.w), n1b = __ldcg(s + i1.x);
    float4 n2 = __ldcg(s + i1.y), n2a = __ldcg(s + i1.z), n2b = __ldcg(s + i1.w);
    float4 r;
    r.x = c.x + 0.5f * (a0.x + a1.x + n1.x + n2.x) + 0.25f * (n1a.x + n1b.x + n2a.x + n2b.x);
    r.y = c.y + 0.5f * (a0.y + a1.y + n1.y + n2.y) + 0.25f * (n1a.y + n1b.y + n2a.y + n2b.y);
    r.z = c.z + 0.5f * (a0.z + a1.z + n1.z + n2.z) + 0.25f * (n1a.z + n1b.z + n2a.z + n2b.z);
    r.w = c.w + 0.5f * (a0.w + a1.w + n1.w + n2.w) + 0.25f * (n1a.w + n1b.w + n2a.w + n2b.w);
    return r;
}

__device__ __forceinline__ float g9s(const int* __restrict__ idx8,
                                     const float* __restrict__ s, int center) {
    int4 i0 = *(const int4*)(idx8);
    int4 i1 = *(const int4*)(idx8 + 4);
    return __ldcg(s + center)
         + 0.5f  * (__ldcg(s + i0.x) + __ldcg(s + i0.y) + __ldcg(s + i0.z) + __ldcg(s + i1.y))
         + 0.25f * (__ldcg(s + i0.w) + __ldcg(s + i1.x) + __ldcg(s + i1.z) + __ldcg(s + i1.w));
}

__global__ void __launch_bounds__(TPB, 4) mega(
        const float4* __restrict__ unary,
        const float*  __restrict__ wsb, const int* __restrict__ osb,
        const int2*   __restrict__ bnb,
        const float*  __restrict__ wss, const int* __restrict__ oss,
        const int2*   __restrict__ bns,
        int Mb, int Ms, float4* __restrict__ outp) {
    const unsigned nb = gridDim.x;
    const int G = gridDim.x * blockDim.x;
    const int t0 = blockIdx.x * blockDim.x + threadIdx.x;

    // ---- P0: build composed stencils; zero scalar + float4 splat buffers ----
    for (int t = t0; t < Mb + Ms; t += G) {
        if (t < Mb) {
#pragma unroll
            for (int p = 0; p < 3; p++) {
                const int2* r1 = bnb + (size_t)(2 * p) * Mb;
                const int2* r2 = bnb + (size_t)(2 * p + 1) * Mb;
                int2 ab = r1[t];
                int2 nn = r2[t];
                int o3 = 0, o4 = 0, o6 = 0, o7 = 0;
                if (nn.x > 0) { int2 c = r1[nn.x - 1]; o3 = c.x; o4 = c.y; }
                if (nn.y > 0) { int2 c = r1[nn.y - 1]; o6 = c.x; o7 = c.y; }
                int4* dst = (int4*)&g_cb[p][(size_t)t * 8];
                dst[0] = make_int4(ab.x, ab.y, nn.x, o3);
                dst[1] = make_int4(o4, nn.y, o6, o7);
            }
        } else {
            int m = t - Mb;
            const int2* r1 = bns;
            const int2* r2 = bns + (size_t)Ms;
            int2 ab = r1[m];
            int2 nn = r2[m];
            int o3 = 0, o4 = 0, o6 = 0, o7 = 0;
            if (nn.x > 0) { int2 c = r1[nn.x - 1]; o3 = c.x; o4 = c.y; }
            if (nn.y > 0) { int2 c = r1[nn.y - 1]; o6 = c.x; o7 = c.y; }
            int4* dst = (int4*)&g_cs9[(size_t)m * 8];
            dst[0] = make_int4(ab.x, ab.y, nn.x, o3);
            dst[1] = make_int4(o4, nn.y, o6, o7);
        }
    }
    for (int i = t0; i <= Mb; i += G) { g_sb[0][i] = 0.f; g_tb[0][i] = make_float4(0.f,0.f,0.f,0.f); }
    for (int i = t0; i <= Ms; i += G) { g_ss[0][i] = 0.f; g_ts[0][i] = make_float4(0.f,0.f,0.f,0.f); }
    gsync(nb);

    // ---- P1: splat ones (scalar) ----
    for (int n = t0; n < NPIX; n += G) {
#pragma unroll
        for (int r = 0; r < D1B; r++)
            red1(&g_sb[0][osb[n * D1B + r]], wsb[n * D1B + r]);
#pragma unroll
        for (int r = 0; r < D1S; r++)
            red1(&g_ss[0][oss[n * D1S + r]], wss[n * D1S + r]);
    }
    gsync(nb);

    // ---- P2: scalar composed pass (0,1) ----
    for (int t = t0; t < Mb + Ms; t += G) {
        if (t < Mb) {
            g_sb[1][t + 1] = g9s(&g_cb[0][(size_t)t * 8], g_sb[0], t + 1);
            if (t == 0) g_sb[1][0] = 0.f;
        } else {
            int m = t - Mb;
            g_ss[1][m + 1] = g9s(&g_cs9[(size_t)m * 8], g_ss[0], m + 1);
            if (m == 0) g_ss[1][0] = 0.f;
        }
    }
    gsync(nb);

    // ---- P3: scalar composed pass (2,3); spatial simple pass 2 ----
    for (int t = t0; t < Mb + Ms; t += G) {
        if (t < Mb) {
            g_sb[0][t + 1] = g9s(&g_cb[1][(size_t)t * 8], g_sb[1], t + 1);
            if (t == 0) g_sb[0][0] = 0.f;
        } else {
            int m = t - Mb;
            int2 nbp = bns[(size_t)2 * Ms + m];
            g_ss[0][m + 1] = __ldcg(&g_ss[1][m + 1])
                           + 0.5f * (__ldcg(&g_ss[1][nbp.x]) + __ldcg(&g_ss[1][nbp.y]));
            if (m == 0) g_ss[0][0] = 0.f;
        }
    }
    gsync(nb);

    // ---- P4: scalar composed pass (4,5) ----
    for (int t = t0; t < Mb; t += G) {
        g_sb[1][t + 1] = g9s(&g_cb[2][(size_t)t * 8], g_sb[0], t + 1);
        if (t == 0) g_sb[1][0] = 0.f;
    }
    gsync(nb);

    // ---- P5: norms + Q0 init + Q0 splat (tb0/ts0 zeroed in P0) ----
    for (int n = t0; n < NPIX; n += G) {
        float sb = 0.f;
#pragma unroll
        for (int r = 0; r < D1B; r++)
            sb += __ldcg(&g_sb[1][osb[n * D1B + r]]) * wsb[n * D1B + r];
        g_inb[n] = 1.0f / (ALPHA_B * sb + 1e-20f);
        float ss = 0.f;
#pragma unroll
        for (int r = 0; r < D1S; r++)
            ss += __ldcg(&g_ss[0][oss[n * D1S + r]]) * wss[n * D1S + r];
        g_ins[n] = 1.0f / (ALPHA_S * ss + 1e-20f);
        float4 q = softmax_neg(unary[n], make_float4(0.f, 0.f, 0.f, 0.f));
#pragma unroll
        for (int r = 0; r < D1B; r++) {
            int o = osb[n * D1B + r];
            float w = wsb[n * D1B + r];
            red4(&g_tb[0][o], q.x * w, q.y * w, q.z * w, q.w * w);
        }
#pragma unroll
        for (int r = 0; r < D1S; r++) {
            int o = oss[n * D1S + r];
            float w = wss[n * D1S + r];
            red4(&g_ts[0][o], q.x * w, q.y * w, q.z * w, q.w * w);
        }
    }
    gsync(nb);

    // ---- 10 mean-field iterations ----
    for (int it = 0; it < 10; it++) {
        // A: bilateral composed (0,1): tb0->tb1 ; spatial composed (0,1): ts0->ts1
        for (int t = t0; t < Mb + Ms; t += G) {
            if (t < Mb) {
                g_tb[1][t + 1] = g9(&g_cb[0][(size_t)t * 8], g_tb[0], t + 1);
                if (t == 0) g_tb[1][0] = make_float4(0.f, 0.f, 0.f, 0.f);
            } else {
                int m = t - Mb;
                g_ts[1][m + 1] = g9(&g_cs9[(size_t)m * 8], g_ts[0], m + 1);
                if (m == 0) g_ts[1][0] = make_float4(0.f, 0.f, 0.f, 0.f);
            }
        }
        gsync(nb);

        // B: bilateral composed (2,3): tb1->tb2 ; spatial simple pass 2: ts1->ts2 ; zero tb0/ts0
        for (int t = t0; t < Mb + Ms; t += G) {
            if (t < Mb) {
                g_tb[2][t + 1] = g9(&g_cb[1][(size_t)t * 8], g_tb[1], t + 1);
                g_tb[0][t + 1] = make_float4(0.f, 0.f, 0.f, 0.f);
                if (t == 0) {
                    g_tb[2][0] = make_float4(0.f, 0.f, 0.f, 0.f);
                    g_tb[0][0] = make_float4(0.f, 0.f, 0.f, 0.f);
                }
            } else {
                int m = t - Mb;
                int2 nbp = bns[(size_t)2 * Ms + m];
                float4 c = __ldcg(&g_ts[1][m + 1]);
                float4 a = __ldcg(&g_ts[1][nbp.x]);
                float4 b = __ldcg(&g_ts[1][nbp.y]);
                g_ts[2][m + 1] = make_float4(c.x + 0.5f * (a.x + b.x), c.y + 0.5f * (a.y + b.y),
                                             c.z + 0.5f * (a.z + b.z), c.w + 0.5f * (a.w + b.w));
                g_ts[0][m + 1] = make_float4(0.f, 0.f, 0.f, 0.f);
                if (m == 0) {
                    g_ts[2][0] = make_float4(0.f, 0.f, 0.f, 0.f);
                    g_ts[0][0] = make_float4(0.f, 0.f, 0.f, 0.f);
                }
            }
        }
        gsync(nb);

        // C: bilateral composed (4,5): tb2->tb1 ; spatial per-pixel message from ts2
        {
            int lim = (Mb > NPIX) ? Mb : NPIX;
            for (int t = t0; t < lim; t += G) {
                if (t < Mb) {
                    g_tb[1][t + 1] = g9(&g_cb[2][(size_t)t * 8], g_tb[2], t + 1);
                    if (t == 0) g_tb[1][0] = make_float4(0.f, 0.f, 0.f, 0.f);
                }
                if (t < NPIX) {
                    float4 fs = make_float4(0.f, 0.f, 0.f, 0.f);
#pragma unroll
                    for (int r = 0; r < D1S; r++) {
                        int o = oss[t * D1S + r];
                        float w = wss[t * D1S + r];
                        float4 v = __ldcg(&g_ts[2][o]);
                        fs.x += v.x * w; fs.y += v.y * w; fs.z += v.z * w; fs.w += v.w * w;
                    }
                    float cs = SP_COMPAT * ALPHA_S * g_ins[t];
                    g_msgS[t] = make_float4(fs.x * cs, fs.y * cs, fs.z * cs, fs.w * cs);
                }
            }
        }
        gsync(nb);

        // D: slice bilateral + msg + softmax; splat next Q (or final write)
        for (int n = t0; n < NPIX; n += G) {
            float4 fb = make_float4(0.f, 0.f, 0.f, 0.f);
            int   ob[D1B];
            float wb[D1B];
#pragma unroll
            for (int r = 0; r < D1B; r++) {
                ob[r] = osb[n * D1B + r];
                wb[r] = wsb[n * D1B + r];
                float4 v = __ldcg(&g_tb[1][ob[r]]);
                fb.x += v.x * wb[r]; fb.y += v.y * wb[r];
                fb.z += v.z * wb[r]; fb.w += v.w * wb[r];
            }
            float cb = BI_COMPAT * ALPHA_B * g_inb[n];
            float4 ms = __ldcg(&g_msgS[n]);
            float4 msg = make_float4(fb.x * cb + ms.x, fb.y * cb + ms.y,
                                     fb.z * cb + ms.z, fb.w * cb + ms.w);
            float4 q = softmax_neg(unary[n], msg);
            if (it == 9) {
                outp[n] = q;
            } else {
#pragma unroll
                for (int r = 0; r < D1B; r++)
                    red4(&g_tb[0][ob[r]], q.x * wb[r], q.y * wb[r], q.z * wb[r], q.w * wb[r]);
#pragma unroll
                for (int r = 0; r < D1S; r++) {
                    int o = oss[n * D1S + r];
                    float w = wss[n * D1S + r];
                    red4(&g_ts[0][o], q.x * w, q.y * w, q.z * w, q.w * w);
                }
            }
        }
        if (it < 9) gsync(nb);
    }
}

extern "C" void kernel_launch(void* const* d_in, const int* in_sizes, int n_in,
                              void* d_out, int out_size) {
    const float4* unary = (const float4*)d_in[0];
    const float*  wsb   = (const float*)d_in[1];
    const int*    osb   = (const int*)d_in[2];
    const int2*   bnb   = (const int2*)d_in[3];
    const float*  wss   = (const float*)d_in[5];
    const int*    oss   = (const int*)d_in[6];
    const int2*   bns   = (const int2*)d_in[7];

    int Mb = in_sizes[3] / (D1B * 2);   // blur_neighbors_bilateral: [6, Mb, 2]
    int Ms = in_sizes[7] / (D1S * 2);   // blur_neighbors_spatial:   [3, Ms, 2]

    int work = Mb + Ms;
    if (work < NPIX) work = NPIX;
    int nb = (work + TPB - 1) / TPB;
    if (nb > MAXBLK) nb = MAXBLK;   // co-residency cap: grid-stride loops absorb remainder

    mega<<<nb, TPB>>>(unary, wsb, osb, bnb, wss, oss, bns, Mb, Ms, (float4*)d_out);
}

// round 11
// speedup vs baseline: 2.2808x; 2.2808x over previous
#include <cuda_runtime.h>

#define NPIX (512*512)
#define D1B 6
#define D1S 3
#define MAXMB (D1B*NPIX+1)
#define MAXMS (D1S*NPIX+1)
#define ALPHA_B (32.0f/33.0f)
#define ALPHA_S 0.8f
#define BI_COMPAT 10.0f
#define SP_COMPAT 3.0f
#define TPB 256

// float4 tables for Q filtering (3-buffer ping-pong per lattice).
__device__ float4 g_tb[3][MAXMB];
__device__ float4 g_ts[3][MAXMS];
// fp32 scalar tables for the ones-filter (2-buffer ping-pong), processed alongside round 0.
__device__ float  g_sb[2][MAXMB];
__device__ float  g_ss[2][MAXMS];
// Composed 2-pass stencil indices: bilateral pairs (0,1),(2,3),(4,5); spatial pair (0,1).
__device__ int    g_cb[3][(size_t)(MAXMB - 1) * 8];
__device__ int    g_cs9[(size_t)(MAXMS - 1) * 8];
__device__ float  g_inb[NPIX];
__device__ float  g_ins[NPIX];

__device__ __forceinline__ void red4(float4* p, float x, float y, float z, float w) {
    asm volatile("red.global.add.v4.f32 [%0], {%1,%2,%3,%4};"
                 :: "l"(p), "f"(x), "f"(y), "f"(z), "f"(w) : "memory");
}
__device__ __forceinline__ void red1(float* p, float v) {
    asm volatile("red.global.add.f32 [%0], %1;" :: "l"(p), "f"(v) : "memory");
}

__device__ __forceinline__ float4 softmax_neg(float4 u, float4 msg) {
    float zx = msg.x - u.x, zy = msg.y - u.y, zz = msg.z - u.z, zw = msg.w - u.w;
    float m = fmaxf(fmaxf(zx, zy), fmaxf(zz, zw));
    float ex = __expf(zx - m), ey = __expf(zy - m), ez = __expf(zz - m), ew = __expf(zw - m);
    float inv = 1.0f / (ex + ey + ez + ew);
    return make_float4(ex * inv, ey * inv, ez * inv, ew * inv);
}

__device__ __forceinline__ float4 gather9(const int4 i0, const int4 i1,
                                          const float4* __restrict__ s, int center) {
    float4 c  = s[center];
    float4 a0 = s[i0.x], a1 = s[i0.y];
    float4 n1 = s[i0.z], n1a = s[i0.w], n1b = s[i1.x];
    float4 n2 = s[i1.y], n2a = s[i1.z], n2b = s[i1.w];
    float4 r;
    r.x = c.x + 0.5f * (a0.x + a1.x + n1.x + n2.x) + 0.25f * (n1a.x + n1b.x + n2a.x + n2b.x);
    r.y = c.y + 0.5f * (a0.y + a1.y + n1.y + n2.y) + 0.25f * (n1a.y + n1b.y + n2a.y + n2b.y);
    r.z = c.z + 0.5f * (a0.z + a1.z + n1.z + n2.z) + 0.25f * (n1a.z + n1b.z + n2a.z + n2b.z);
    r.w = c.w + 0.5f * (a0.w + a1.w + n1.w + n2.w) + 0.25f * (n1a.w + n1b.w + n2a.w + n2b.w);
    return r;
}

__device__ __forceinline__ float gather9s(const int4 i0, const int4 i1,
                                          const float* __restrict__ s, int center) {
    return s[center]
         + 0.5f  * (s[i0.x] + s[i0.y] + s[i0.z] + s[i1.y])
         + 0.25f * (s[i0.w] + s[i1.x] + s[i1.z] + s[i1.w]);
}

// P0: build composed 2-pass stencils; zero all splat buffers (scalar + float4).
__global__ void __launch_bounds__(TPB) compose_zero(const int2* __restrict__ bnb, int Mb,
                                                    const int2* __restrict__ bns, int Ms) {
    int t = blockIdx.x * blockDim.x + threadIdx.x;
    if (t <= Mb) { g_sb[0][t] = 0.f; g_tb[0][t] = make_float4(0.f, 0.f, 0.f, 0.f); }
    if (t <= Ms) { g_ss[0][t] = 0.f; g_ts[0][t] = make_float4(0.f, 0.f, 0.f, 0.f); }
    if (t < Mb) {
#pragma unroll
        for (int p = 0; p < 3; p++) {
            const int2* r1 = bnb + (size_t)(2 * p) * Mb;
            const int2* r2 = bnb + (size_t)(2 * p + 1) * Mb;
            int2 ab = r1[t];
            int2 nn = r2[t];
            int o3 = 0, o4 = 0, o6 = 0, o7 = 0;
            if (nn.x > 0) { int2 c = r1[nn.x - 1]; o3 = c.x; o4 = c.y; }
            if (nn.y > 0) { int2 c = r1[nn.y - 1]; o6 = c.x; o7 = c.y; }
            int4* dst = (int4*)&g_cb[p][(size_t)t * 8];
            dst[0] = make_int4(ab.x, ab.y, nn.x, o3);
            dst[1] = make_int4(o4, nn.y, o6, o7);
        }
    } else {
        int m = t - Mb;
        if (m < Ms) {
            const int2* r1 = bns;
            const int2* r2 = bns + (size_t)Ms;
            int2 ab = r1[m];
            int2 nn = r2[m];
            int o3 = 0, o4 = 0, o6 = 0, o7 = 0;
            if (nn.x > 0) { int2 c = r1[nn.x - 1]; o3 = c.x; o4 = c.y; }
            if (nn.y > 0) { int2 c = r1[nn.y - 1]; o6 = c.x; o7 = c.y; }
            int4* dst = (int4*)&g_cs9[(size_t)m * 8];
            dst[0] = make_int4(ab.x, ab.y, nn.x, o3);
            dst[1] = make_int4(o4, nn.y, o6, o7);
        }
    }
}

// P1: Q0 = softmax(-u); splat ones (scalar) AND Q0 (float4), one idx read.
__global__ void __launch_bounds__(TPB) splat0(
        const float4* __restrict__ unary,
        const int* __restrict__ osb, const float* __restrict__ wsb,
        const int* __restrict__ oss, const float* __restrict__ wss) {
    int n = blockIdx.x * blockDim.x + threadIdx.x;
    if (n >= NPIX) return;
    float4 q = softmax_neg(unary[n], make_float4(0.f, 0.f, 0.f, 0.f));
#pragma unroll
    for (int r = 0; r < D1B; r++) {
        int o = osb[n * D1B + r];
        float w = wsb[n * D1B + r];
        red1(&g_sb[0][o], w);
        red4(&g_tb[0][o], q.x * w, q.y * w, q.z * w, q.w * w);
    }
#pragma unroll
    for (int r = 0; r < D1S; r++) {
        int o = oss[n * D1S + r];
        float w = wss[n * D1S + r];
        red1(&g_ss[0][o], w);
        red4(&g_ts[0][o], q.x * w, q.y * w, q.z * w, q.w * w);
    }
}

// ---------------- Blur kernels. FUSE_ONES=1 variants also blur the scalar
// ones-tables, reusing the already-loaded stencil indices (round 0 only). ----

template<int FUSE_ONES>
__global__ void __launch_bounds__(TPB) k1t(int Mb, int Ms) {
    int t = blockIdx.x * blockDim.x + threadIdx.x;
    if (t < Mb) {
        const int4* ip = (const int4*)&g_cb[0][(size_t)t * 8];
        int4 i0 = ip[0], i1 = ip[1];
        g_tb[1][t + 1] = gather9(i0, i1, g_tb[0], t + 1);
        if (FUSE_ONES) g_sb[1][t + 1] = gather9s(i0, i1, g_sb[0], t + 1);
        if (t == 0) {
            g_tb[1][0] = make_float4(0.f, 0.f, 0.f, 0.f);
            if (FUSE_ONES) g_sb[1][0] = 0.f;
        }
    } else {
        int m = t - Mb;
        if (m < Ms) {
            const int4* ip = (const int4*)&g_cs9[(size_t)m * 8];
            int4 i0 = ip[0], i1 = ip[1];
            g_ts[1][m + 1] = gather9(i0, i1, g_ts[0], m + 1);
            if (FUSE_ONES) g_ss[1][m + 1] = gather9s(i0, i1, g_ss[0], m + 1);
            if (m == 0) {
                g_ts[1][0] = make_float4(0.f, 0.f, 0.f, 0.f);
                if (FUSE_ONES) g_ss[1][0] = 0.f;
            }
        }
    }
}

template<int FUSE_ONES>
__global__ void __launch_bounds__(TPB) k2t(int Mb, const int2* __restrict__ bns, int Ms) {
    int t = blockIdx.x * blockDim.x + threadIdx.x;
    if (t < Mb) {
        const int4* ip = (const int4*)&g_cb[1][(size_t)t * 8];
        int4 i0 = ip[0], i1 = ip[1];
        g_tb[2][t + 1] = gather9(i0, i1, g_tb[1], t + 1);
        if (FUSE_ONES) g_sb[0][t + 1] = gather9s(i0, i1, g_sb[1], t + 1);
        g_tb[0][t + 1] = make_float4(0.f, 0.f, 0.f, 0.f);
        if (t == 0) {
            g_tb[2][0] = make_float4(0.f, 0.f, 0.f, 0.f);
            g_tb[0][0] = make_float4(0.f, 0.f, 0.f, 0.f);
            if (FUSE_ONES) g_sb[0][0] = 0.f;
        }
    } else {
        int m = t - Mb;
        if (m < Ms) {
            int2 nb = bns[(size_t)2 * Ms + m];
            const float4* __restrict__ s = g_ts[1];
            float4 c = s[m + 1], a = s[nb.x], b = s[nb.y];
            g_ts[2][m + 1] = make_float4(c.x + 0.5f * (a.x + b.x), c.y + 0.5f * (a.y + b.y),
                                         c.z + 0.5f * (a.z + b.z), c.w + 0.5f * (a.w + b.w));
            if (FUSE_ONES)
                g_ss[0][m + 1] = g_ss[1][m + 1] + 0.5f * (g_ss[1][nb.x] + g_ss[1][nb.y]);
            g_ts[0][m + 1] = make_float4(0.f, 0.f, 0.f, 0.f);
            if (m == 0) {
                g_ts[2][0] = make_float4(0.f, 0.f, 0.f, 0.f);
                g_ts[0][0] = make_float4(0.f, 0.f, 0.f, 0.f);
                if (FUSE_ONES) g_ss[0][0] = 0.f;
            }
        }
    }
}

template<int FUSE_ONES>
__global__ void __launch_bounds__(TPB) k3t(int Mb) {
    int t = blockIdx.x * blockDim.x + threadIdx.x;
    if (t >= Mb) return;
    const int4* ip = (const int4*)&g_cb[2][(size_t)t * 8];
    int4 i0 = ip[0], i1 = ip[1];
    g_tb[1][t + 1] = gather9(i0, i1, g_tb[2], t + 1);
    if (FUSE_ONES) g_sb[1][t + 1] = gather9s(i0, i1, g_sb[0], t + 1);
    if (t == 0) {
        g_tb[1][0] = make_float4(0.f, 0.f, 0.f, 0.f);
        if (FUSE_ONES) g_sb[1][0] = 0.f;
    }
}

// Slice + mean-field update + splat of next Q (or final write). Round 0
// (NORM=1) additionally computes the norms inline from the blurred ones-tables.
template<int NORM>
__global__ void __launch_bounds__(TPB) slice_t(
        const float4* __restrict__ unary,
        const int* __restrict__ osb, const float* __restrict__ wsb,
        const int* __restrict__ oss, const float* __restrict__ wss,
        float4* __restrict__ outp, int write_out) {
    int n = blockIdx.x * blockDim.x + threadIdx.x;
    if (n >= NPIX) return;
    float4 fb = make_float4(0.f, 0.f, 0.f, 0.f);
    float  nb = 0.f;
    int   ob[D1B];
    float wb[D1B];
#pragma unroll
    for (int r = 0; r < D1B; r++) {
        ob[r] = osb[n * D1B + r];
        wb[r] = wsb[n * D1B + r];
        float4 v = g_tb[1][ob[r]];
        fb.x += v.x * wb[r]; fb.y += v.y * wb[r]; fb.z += v.z * wb[r]; fb.w += v.w * wb[r];
        if (NORM) nb += g_sb[1][ob[r]] * wb[r];
    }
    float4 fs = make_float4(0.f, 0.f, 0.f, 0.f);
    float  ns = 0.f;
    int   osr[D1S];
    float wsr[D1S];
#pragma unroll
    for (int r = 0; r < D1S; r++) {
        osr[r] = oss[n * D1S + r];
        wsr[r] = wss[n * D1S + r];
        float4 v = g_ts[2][osr[r]];
        fs.x += v.x * wsr[r]; fs.y += v.y * wsr[r]; fs.z += v.z * wsr[r]; fs.w += v.w * wsr[r];
        if (NORM) ns += g_ss[0][osr[r]] * wsr[r];
    }
    float inb, ins;
    if (NORM) {
        inb = 1.0f / (ALPHA_B * nb + 1e-20f);
        ins = 1.0f / (ALPHA_S * ns + 1e-20f);
        g_inb[n] = inb;
        g_ins[n] = ins;
    } else {
        inb = g_inb[n];
        ins = g_ins[n];
    }
    float cb = BI_COMPAT * ALPHA_B * inb;
    float cs = SP_COMPAT * ALPHA_S * ins;
    float4 msg = make_float4(fb.x * cb + fs.x * cs, fb.y * cb + fs.y * cs,
                             fb.z * cb + fs.z * cs, fb.w * cb + fs.w * cs);
    float4 q = softmax_neg(unary[n], msg);
    if (write_out) {
        outp[n] = q;
    } else {
#pragma unroll
        for (int r = 0; r < D1B; r++)
            red4(&g_tb[0][ob[r]], q.x * wb[r], q.y * wb[r], q.z * wb[r], q.w * wb[r]);
#pragma unroll
        for (int r = 0; r < D1S; r++)
            red4(&g_ts[0][osr[r]], q.x * wsr[r], q.y * wsr[r], q.z * wsr[r], q.w * wsr[r]);
    }
}

extern "C" void kernel_launch(void* const* d_in, const int* in_sizes, int n_in,
                              void* d_out, int out_size) {
    const float4* unary = (const float4*)d_in[0];
    const float*  wsb   = (const float*)d_in[1];
    const int*    osb   = (const int*)d_in[2];
    const int2*   bnb   = (const int2*)d_in[3];
    const float*  wss   = (const float*)d_in[5];
    const int*    oss   = (const int*)d_in[6];
    const int2*   bns   = (const int2*)d_in[7];

    int Mb = in_sizes[3] / (D1B * 2);   // blur_neighbors_bilateral: [6, Mb, 2]
    int Ms = in_sizes[7] / (D1S * 2);   // blur_neighbors_spatial:   [3, Ms, 2]

    const int nblk = (NPIX + TPB - 1) / TPB;
    const int cblk = (Mb + Ms + TPB - 1) / TPB;
    const int bblk = (Mb + TPB - 1) / TPB;

    // ---- Init: stencils + zero, then fused ones+Q0 splat ----
    compose_zero<<<cblk, TPB>>>(bnb, Mb, bns, Ms);
    splat0<<<nblk, TPB>>>(unary, osb, wsb, oss, wss);

    // ---- Round 0: blur ones alongside Q, compute norms inline in slice ----
    k1t<1><<<cblk, TPB>>>(Mb, Ms);
    k2t<1><<<cblk, TPB>>>(Mb, bns, Ms);
    k3t<1><<<bblk, TPB>>>(Mb);
    slice_t<1><<<nblk, TPB>>>(unary, osb, wsb, oss, wss, (float4*)d_out, 0);

    // ---- Rounds 1-9 ----
    for (int it = 1; it < 10; it++) {
        k1t<0><<<cblk, TPB>>>(Mb, Ms);
        k2t<0><<<cblk, TPB>>>(Mb, bns, Ms);
        k3t<0><<<bblk, TPB>>>(Mb);
        slice_t<0><<<nblk, TPB>>>(unary, osb, wsb, oss, wss,
                                  (float4*)d_out, it == 9 ? 1 : 0);
    }
}